// round 9
// baseline (speedup 1.0000x reference)
#include <cuda_runtime.h>
#include <cuda_bf16.h>
#include <stdint.h>

#define N_NODES 50000
#define E_EDGES 800000
#define IN_C    10
#define HID     96
#define OUT_C   48
#define SCAN_B  196          // ceil(50000/256)

// ---- scratch (device globals; no allocation allowed) ----
__device__ int   g_cnt[N_NODES];
__device__ int   g_bsum[256];
__device__ int   g_boff[256];
__device__ int   g_off[N_NODES + 1];
__device__ int   g_cur[N_NODES];
__device__ float g_dis[N_NODES];
__device__ int   g_src[E_EDGES];            // CSR src indices only
__device__ float g_xs [N_NODES * IN_C];     // x * dis (row-scaled)
__device__ float g_hs [N_NODES * HID];      // relu(h) * dis
__device__ float g_aggh[N_NODES * HID];

__global__ void k_zero_cnt() {
    int n = blockIdx.x * blockDim.x + threadIdx.x;
    if (n < N_NODES) g_cnt[n] = 0;
}

__global__ void k_count(const int* __restrict__ ei) {
    int t = blockIdx.x * blockDim.x + threadIdx.x;
    if (t * 2 >= E_EDGES) return;
    int2 c2 = __ldg((const int2*)(ei + E_EDGES) + t);
    atomicAdd(&g_cnt[c2.x], 1);
    atomicAdd(&g_cnt[c2.y], 1);
}

__global__ void k_blocksum() {
    __shared__ int wsum[8];
    int idx = blockIdx.x * 256 + threadIdx.x;
    int v = (idx < N_NODES) ? g_cnt[idx] : 0;
    int s = v;
    #pragma unroll
    for (int o = 16; o > 0; o >>= 1) s += __shfl_down_sync(0xffffffffu, s, o);
    if ((threadIdx.x & 31) == 0) wsum[threadIdx.x >> 5] = s;
    __syncthreads();
    if (threadIdx.x < 8) {
        int t = wsum[threadIdx.x];
        #pragma unroll
        for (int o = 4; o > 0; o >>= 1) t += __shfl_down_sync(0xffu, t, o);
        if (threadIdx.x == 0) g_bsum[blockIdx.x] = t;
    }
}

__global__ void k_scanmid() {
    __shared__ int ws[8];
    int t = threadIdx.x;
    int v = (t < SCAN_B) ? g_bsum[t] : 0;
    int inc = v;
    #pragma unroll
    for (int o = 1; o < 32; o <<= 1) {
        int u = __shfl_up_sync(0xffffffffu, inc, o);
        if ((t & 31) >= o) inc += u;
    }
    if ((t & 31) == 31) ws[t >> 5] = inc;
    __syncthreads();
    if (t < 8) {
        int wv = ws[t];
        int winc = wv;
        #pragma unroll
        for (int o = 1; o < 8; o <<= 1) {
            int u = __shfl_up_sync(0xffu, winc, o);
            if (t >= o) winc += u;
        }
        ws[t] = winc - wv;
    }
    __syncthreads();
    if (t < SCAN_B) g_boff[t] = inc - v + ws[t >> 5];
    if (t == 0) g_off[N_NODES] = E_EDGES;
}

__global__ void k_apply() {
    __shared__ int ws[8];
    int idx = blockIdx.x * 256 + threadIdx.x;
    int t = threadIdx.x;
    int v = (idx < N_NODES) ? g_cnt[idx] : 0;
    int inc = v;
    #pragma unroll
    for (int o = 1; o < 32; o <<= 1) {
        int u = __shfl_up_sync(0xffffffffu, inc, o);
        if ((t & 31) >= o) inc += u;
    }
    if ((t & 31) == 31) ws[t >> 5] = inc;
    __syncthreads();
    if (t < 8) {
        int wv = ws[t];
        int winc = wv;
        #pragma unroll
        for (int o = 1; o < 8; o <<= 1) {
            int u = __shfl_up_sync(0xffu, winc, o);
            if (t >= o) winc += u;
        }
        ws[t] = winc - wv;
    }
    __syncthreads();
    if (idx < N_NODES) {
        int off = g_boff[blockIdx.x] + ws[t >> 5] + (inc - v);
        g_off[idx] = off;
        g_cur[idx] = off;
        g_dis[idx] = rsqrtf((float)(v + 1));
    }
}

// xs = x * dis (row-scaled)
__global__ void k_xs(const float* __restrict__ x) {
    int t = blockIdx.x * blockDim.x + threadIdx.x;
    if (t < N_NODES * IN_C) g_xs[t] = __ldg(&x[t]) * g_dis[t / IN_C];
}

// CSR fill: only src index
__global__ void k_fill(const int* __restrict__ ei) {
    int e = blockIdx.x * blockDim.x + threadIdx.x;
    if (e >= E_EDGES) return;
    int row = __ldg(&ei[e]);
    int col = __ldg(&ei[E_EDGES + e]);
    int pos = atomicAdd(&g_cur[col], 1);
    g_src[pos] = row;
}

// Fused: agg_x = dis[n]*(xs[n] + sum xs[src]) ; h = relu(agg @ W1 + b1) ;
// store hs = h*dis[n].  block = (96,4).
__global__ void k_fused1(const float* __restrict__ W1,
                         const float* __restrict__ b1) {
    __shared__ float part[4][9][10];
    __shared__ float sagg[4][10];
    __shared__ float sW1[IN_C * HID];
    __shared__ float sb1[HID];
    int tx = threadIdx.x, ty = threadIdx.y;
    int tid = ty * 96 + tx;
    for (int t = tid; t < IN_C * HID; t += 384) sW1[t] = W1[t];
    if (tid < HID) sb1[tid] = b1[tid];
    int n = blockIdx.x * 4 + ty;

    int g = tx / 10;
    int c = tx - g * 10;
    if (tx < 90 && n < N_NODES) {
        float p = 0.0f;
        int s = g_off[n], e = g_off[n + 1];
        for (int i = s + g; i < e; i += 9)
            p += __ldg(&g_xs[(size_t)__ldg(&g_src[i]) * IN_C + c]);
        part[ty][g][c] = p;
    }
    __syncthreads();
    if (tx < IN_C && n < N_NODES) {
        float a = g_xs[(size_t)n * IN_C + tx];
        #pragma unroll
        for (int g2 = 0; g2 < 9; g2++) a += part[ty][g2][tx];
        sagg[ty][tx] = a * g_dis[n];
    }
    __syncthreads();
    if (n >= N_NODES) return;
    float acc = sb1[tx];
    #pragma unroll
    for (int cc = 0; cc < IN_C; cc++)
        acc += sagg[ty][cc] * sW1[cc * HID + tx];
    g_hs[(size_t)n * HID + tx] = fmaxf(acc, 0.0f) * g_dis[n];
}

// agg_h[n][j] = dis[n] * (hs[n][j] + sum_e hs[src][j])   (pure gather-sum)
__global__ void k_aggh_csr() {
    int n = blockIdx.x * 4 + threadIdx.y;
    if (n >= N_NODES) return;
    int j = threadIdx.x;
    float acc = g_hs[(size_t)n * HID + j];
    int s = g_off[n], e = g_off[n + 1];
    int cnt4 = (e - s) & ~3;
    int i = s;
    for (; i < s + cnt4; i += 4) {
        int s0 = __ldg(&g_src[i]);
        int s1 = __ldg(&g_src[i + 1]);
        int s2 = __ldg(&g_src[i + 2]);
        int s3 = __ldg(&g_src[i + 3]);
        float v0 = __ldg(&g_hs[(size_t)s0 * HID + j]);
        float v1 = __ldg(&g_hs[(size_t)s1 * HID + j]);
        float v2 = __ldg(&g_hs[(size_t)s2 * HID + j]);
        float v3 = __ldg(&g_hs[(size_t)s3 * HID + j]);
        acc += v0 + v1 + v2 + v3;
    }
    for (; i < e; i++)
        acc += __ldg(&g_hs[(size_t)__ldg(&g_src[i]) * HID + j]);
    g_aggh[(size_t)n * HID + j] = acc * g_dis[n];
}

// Output GEMM: block (12,8) = 96 thr; thread = 8 j-cols x 8 nodes; 64 nodes/blk.
#define ONPB 64
__global__ void k_out(const float* __restrict__ Wmu,
                      const float* __restrict__ bmu,
                      const float* __restrict__ Wls,
                      const float* __restrict__ bls,
                      float* __restrict__ out) {
    __shared__ __align__(16) float sW[24 * HID];
    __shared__ float sh[ONPB * 97];
    __shared__ float sb[HID];
    int tx = threadIdx.x, ty = threadIdx.y;
    int tid = ty * 12 + tx;
    int base = blockIdx.x * ONPB;

    if (tid < HID)
        sb[tid] = (tid < OUT_C) ? __ldg(&bmu[tid]) : __ldg(&bls[tid - OUT_C]);
    for (int t = tid; t < ONPB * 24; t += 96) {
        int nd = t / 24, c4 = (t - nd * 24) * 4;
        int n = base + nd;
        float4 v = (n < N_NODES) ? __ldg((const float4*)&g_aggh[(size_t)n * HID + c4])
                                 : make_float4(0.f, 0.f, 0.f, 0.f);
        float* dst = &sh[nd * 97 + c4];
        dst[0] = v.x; dst[1] = v.y; dst[2] = v.z; dst[3] = v.w;
    }

    int j8 = tx * 8;
    float4 acc0[8], acc1[8];
    {
        __syncthreads();
        float4 b0 = *(const float4*)&sb[j8];
        float4 b1v = *(const float4*)&sb[j8 + 4];
        #pragma unroll
        for (int k = 0; k < 8; k++) { acc0[k] = b0; acc1[k] = b1v; }
    }

    #pragma unroll
    for (int cb = 0; cb < 4; cb++) {
        for (int t = tid; t < 24 * 24; t += 96) {
            int r = t / 24, q4 = (t - r * 24) * 4;
            int c = cb * 24 + r;
            float4 w;
            if (q4 < OUT_C && q4 + 3 < OUT_C) {
                w = __ldg((const float4*)&Wmu[c * OUT_C + q4]);
            } else {
                w = __ldg((const float4*)&Wls[c * OUT_C + (q4 - OUT_C)]);
            }
            *(float4*)&sW[r * HID + q4] = w;
        }
        __syncthreads();
        #pragma unroll 4
        for (int c = 0; c < 24; c++) {
            float4 w0 = *(const float4*)&sW[c * HID + j8];
            float4 w1 = *(const float4*)&sW[c * HID + j8 + 4];
            #pragma unroll
            for (int k = 0; k < 8; k++) {
                float a = sh[(ty * 8 + k) * 97 + cb * 24 + c];
                acc0[k].x += a * w0.x; acc0[k].y += a * w0.y;
                acc0[k].z += a * w0.z; acc0[k].w += a * w0.w;
                acc1[k].x += a * w1.x; acc1[k].y += a * w1.y;
                acc1[k].z += a * w1.z; acc1[k].w += a * w1.w;
            }
        }
        __syncthreads();
    }

    #pragma unroll
    for (int k = 0; k < 8; k++) {
        int n = base + ty * 8 + k;
        if (n >= N_NODES) continue;
        if (j8 < OUT_C) {
            *(float4*)&out[(size_t)n * OUT_C + j8] = acc0[k];
            *(float4*)&out[(size_t)n * OUT_C + j8 + 4] = acc1[k];
        } else {
            size_t o = (size_t)N_NODES * OUT_C + (size_t)n * OUT_C + (j8 - OUT_C);
            *(float4*)&out[o] = acc0[k];
            *(float4*)&out[o + 4] = acc1[k];
        }
    }
}

extern "C" void kernel_launch(void* const* d_in, const int* in_sizes, int n_in,
                              void* d_out, int out_size) {
    const float* x   = (const float*)d_in[0];
    const int*   ei  = (const int*)d_in[1];
    const float* W1  = (const float*)d_in[2];
    const float* b1  = (const float*)d_in[3];
    const float* Wmu = (const float*)d_in[4];
    const float* bmu = (const float*)d_in[5];
    const float* Wls = (const float*)d_in[6];
    const float* bls = (const float*)d_in[7];
    float* out = (float*)d_out;

    k_zero_cnt<<<(N_NODES + 255) / 256, 256>>>();
    k_count<<<(E_EDGES / 2 + 255) / 256, 256>>>(ei);
    k_blocksum<<<SCAN_B, 256>>>();
    k_scanmid<<<1, 256>>>();
    k_apply<<<SCAN_B, 256>>>();
    k_xs<<<(N_NODES * IN_C + 255) / 256, 256>>>(x);
    k_fill<<<(E_EDGES + 255) / 256, 256>>>(ei);
    k_fused1<<<(N_NODES + 3) / 4, dim3(96, 4)>>>(W1, b1);
    k_aggh_csr<<<(N_NODES + 3) / 4, dim3(HID, 4)>>>();
    k_out<<<(N_NODES + ONPB - 1) / ONPB, dim3(12, 8)>>>(Wmu, bmu, Wls, bls, out);
}

// round 10
// speedup vs baseline: 1.0022x; 1.0022x over previous
#include <cuda_runtime.h>
#include <cuda_bf16.h>
#include <stdint.h>

#define N_NODES 50000
#define E_EDGES 800000
#define IN_C    10
#define HID     96
#define OUT_C   48
#define SCAN_B  196          // ceil(50000/256)
#define FLAGB   (1 << 30)

// ---- scratch (device globals; zero-init at module load) ----
__device__ int   g_cnt[N_NODES];
__device__ int   g_pub[256];                // decoupled-lookback (flag|agg)
__device__ int   g_off[N_NODES + 1];
__device__ int   g_cur[N_NODES];
__device__ float g_dis[N_NODES];
__device__ int   g_src[E_EDGES];            // CSR src indices
__device__ float g_xs [N_NODES * IN_C];     // x * dis
__device__ float g_hs [N_NODES * HID];      // relu(h) * dis
__device__ float g_aggh[N_NODES * HID];

// count: 2 edges per thread (cnt zeroed by k_fill of the previous call;
// device globals are zero-initialized, so the first call is also correct)
__global__ void k_count(const int* __restrict__ ei) {
    int t = blockIdx.x * blockDim.x + threadIdx.x;
    if (t * 2 >= E_EDGES) return;
    int2 c2 = __ldg((const int2*)(ei + E_EDGES) + t);
    atomicAdd(&g_cnt[c2.x], 1);
    atomicAdd(&g_cnt[c2.y], 1);
}

// Single-pass scan with decoupled lookback + dis + cursors + xs.
// Publish packs (FLAGB | aggregate) in one int -> no fence ordering needed.
__global__ void k_scanfuse(const float* __restrict__ x) {
    __shared__ int ws[8];
    __shared__ int s_prefix;
    int b = blockIdx.x, t = threadIdx.x;
    int idx = b * 256 + t;
    int v = (idx < N_NODES) ? g_cnt[idx] : 0;
    int inc = v;
    #pragma unroll
    for (int o = 1; o < 32; o <<= 1) {
        int u = __shfl_up_sync(0xffffffffu, inc, o);
        if ((t & 31) >= o) inc += u;
    }
    if ((t & 31) == 31) ws[t >> 5] = inc;
    __syncthreads();
    if (t < 8) {
        int wv = ws[t];
        int winc = wv;
        #pragma unroll
        for (int o = 1; o < 8; o <<= 1) {
            int u = __shfl_up_sync(0xffu, winc, o);
            if (t >= o) winc += u;
        }
        ws[t] = winc - wv;                     // exclusive warp offset
        if (t == 7)
            *((volatile int*)&g_pub[b]) = winc | FLAGB;   // publish aggregate
    }
    __syncwarp(0xffffffffu);
    if (t < 32) {                              // lookback over predecessors
        int sum = 0;
        for (int p = t; p < b; p += 32) {
            int pv;
            do { pv = *((volatile int*)&g_pub[p]); } while (!(pv & FLAGB));
            sum += pv & ~FLAGB;
        }
        #pragma unroll
        for (int o = 16; o > 0; o >>= 1)
            sum += __shfl_down_sync(0xffffffffu, sum, o);
        if (t == 0) s_prefix = sum;
    }
    __syncthreads();
    if (idx < N_NODES) {
        int off = s_prefix + ws[t >> 5] + (inc - v);
        g_off[idx] = off;
        g_cur[idx] = off;
        float d = rsqrtf((float)(v + 1));
        g_dis[idx] = d;
        const float* xr = x + (size_t)idx * IN_C;
        float* xo = g_xs + (size_t)idx * IN_C;
        #pragma unroll
        for (int c = 0; c < IN_C; c++) xo[c] = __ldg(&xr[c]) * d;
    }
    if (idx == 0) g_off[N_NODES] = E_EDGES;
}

// CSR fill (src only) + reset cnt/pub for the next call
__global__ void k_fill(const int* __restrict__ ei) {
    int e = blockIdx.x * blockDim.x + threadIdx.x;
    if (e < 256) g_pub[e] = 0;
    if (e < N_NODES) g_cnt[e] = 0;
    if (e >= E_EDGES) return;
    int row = __ldg(&ei[e]);
    int col = __ldg(&ei[E_EDGES + e]);
    int pos = atomicAdd(&g_cur[col], 1);
    g_src[pos] = row;
}

// Fused: agg_x = dis[n]*(xs[n] + sum xs[src]) ; h = relu(agg @ W1 + b1) ;
// store hs = h*dis[n].  block = (96,4); stage1 = 9 groups x 10 ch, 2-wide MLP.
__global__ void k_fused1(const float* __restrict__ W1,
                         const float* __restrict__ b1) {
    __shared__ float part[4][9][10];
    __shared__ float sagg[4][10];
    __shared__ float sW1[IN_C * HID];
    __shared__ float sb1[HID];
    int tx = threadIdx.x, ty = threadIdx.y;
    int tid = ty * 96 + tx;
    for (int t = tid; t < IN_C * HID; t += 384) sW1[t] = W1[t];
    if (tid < HID) sb1[tid] = b1[tid];
    int n = blockIdx.x * 4 + ty;

    int g = tx / 10;
    int c = tx - g * 10;
    if (tx < 90 && n < N_NODES) {
        float p = 0.0f;
        int s = g_off[n], e = g_off[n + 1];
        int last = e - 1;
        for (int i = s + g; i < e; i += 18) {
            int i2 = min(i + 9, last);
            int s0 = __ldg(&g_src[i]);
            int s1 = __ldg(&g_src[i2]);
            float v0 = __ldg(&g_xs[(size_t)s0 * IN_C + c]);
            float v1 = __ldg(&g_xs[(size_t)s1 * IN_C + c]);
            p += v0 + ((i + 9 <= last) ? v1 : 0.0f);
        }
        part[ty][g][c] = p;
    }
    __syncthreads();
    if (tx < IN_C && n < N_NODES) {
        float a = g_xs[(size_t)n * IN_C + tx];
        #pragma unroll
        for (int g2 = 0; g2 < 9; g2++) a += part[ty][g2][tx];
        sagg[ty][tx] = a * g_dis[n];
    }
    __syncthreads();
    if (n >= N_NODES) return;
    float acc = sb1[tx];
    #pragma unroll
    for (int cc = 0; cc < IN_C; cc++)
        acc += sagg[ty][cc] * sW1[cc * HID + tx];
    g_hs[(size_t)n * HID + tx] = fmaxf(acc, 0.0f) * g_dis[n];
}

// agg_h[n][j] = dis[n]*(hs[n][j] + sum hs[src][j]); branch-free 8-wide MLP
__global__ void k_aggh_csr() {
    int n = blockIdx.x * 4 + threadIdx.y;
    if (n >= N_NODES) return;
    int j = threadIdx.x;
    float acc = g_hs[(size_t)n * HID + j];
    int s = g_off[n], e = g_off[n + 1];
    int last = e - 1;
    for (int i = s; i < e; i += 8) {
        #pragma unroll
        for (int k = 0; k < 8; k++) {
            int ik = min(i + k, last);
            int sk = __ldg(&g_src[ik]);
            float vv = __ldg(&g_hs[(size_t)sk * HID + j]);
            acc += (i + k <= last) ? vv : 0.0f;
        }
    }
    g_aggh[(size_t)n * HID + j] = acc * g_dis[n];
}

// Output GEMM: block (12,8) = 96 thr; thread = 8 j-cols x 8 nodes; 64 nodes/blk.
#define ONPB 64
__global__ void k_out(const float* __restrict__ Wmu,
                      const float* __restrict__ bmu,
                      const float* __restrict__ Wls,
                      const float* __restrict__ bls,
                      float* __restrict__ out) {
    __shared__ __align__(16) float sW[24 * HID];
    __shared__ float sh[ONPB * 97];
    __shared__ float sb[HID];
    int tx = threadIdx.x, ty = threadIdx.y;
    int tid = ty * 12 + tx;
    int base = blockIdx.x * ONPB;

    if (tid < HID)
        sb[tid] = (tid < OUT_C) ? __ldg(&bmu[tid]) : __ldg(&bls[tid - OUT_C]);
    for (int t = tid; t < ONPB * 24; t += 96) {
        int nd = t / 24, c4 = (t - nd * 24) * 4;
        int n = base + nd;
        float4 v = (n < N_NODES) ? __ldg((const float4*)&g_aggh[(size_t)n * HID + c4])
                                 : make_float4(0.f, 0.f, 0.f, 0.f);
        float* dst = &sh[nd * 97 + c4];
        dst[0] = v.x; dst[1] = v.y; dst[2] = v.z; dst[3] = v.w;
    }

    int j8 = tx * 8;
    float4 acc0[8], acc1[8];
    {
        __syncthreads();
        float4 b0 = *(const float4*)&sb[j8];
        float4 b1v = *(const float4*)&sb[j8 + 4];
        #pragma unroll
        for (int k = 0; k < 8; k++) { acc0[k] = b0; acc1[k] = b1v; }
    }

    #pragma unroll
    for (int cb = 0; cb < 4; cb++) {
        for (int t = tid; t < 24 * 24; t += 96) {
            int r = t / 24, q4 = (t - r * 24) * 4;
            int c = cb * 24 + r;
            float4 w;
            if (q4 < OUT_C && q4 + 3 < OUT_C) {
                w = __ldg((const float4*)&Wmu[c * OUT_C + q4]);
            } else {
                w = __ldg((const float4*)&Wls[c * OUT_C + (q4 - OUT_C)]);
            }
            *(float4*)&sW[r * HID + q4] = w;
        }
        __syncthreads();
        #pragma unroll 4
        for (int c = 0; c < 24; c++) {
            float4 w0 = *(const float4*)&sW[c * HID + j8];
            float4 w1 = *(const float4*)&sW[c * HID + j8 + 4];
            #pragma unroll
            for (int k = 0; k < 8; k++) {
                float a = sh[(ty * 8 + k) * 97 + cb * 24 + c];
                acc0[k].x += a * w0.x; acc0[k].y += a * w0.y;
                acc0[k].z += a * w0.z; acc0[k].w += a * w0.w;
                acc1[k].x += a * w1.x; acc1[k].y += a * w1.y;
                acc1[k].z += a * w1.z; acc1[k].w += a * w1.w;
            }
        }
        __syncthreads();
    }

    #pragma unroll
    for (int k = 0; k < 8; k++) {
        int n = base + ty * 8 + k;
        if (n >= N_NODES) continue;
        if (j8 < OUT_C) {
            *(float4*)&out[(size_t)n * OUT_C + j8] = acc0[k];
            *(float4*)&out[(size_t)n * OUT_C + j8 + 4] = acc1[k];
        } else {
            size_t o = (size_t)N_NODES * OUT_C + (size_t)n * OUT_C + (j8 - OUT_C);
            *(float4*)&out[o] = acc0[k];
            *(float4*)&out[o + 4] = acc1[k];
        }
    }
}

extern "C" void kernel_launch(void* const* d_in, const int* in_sizes, int n_in,
                              void* d_out, int out_size) {
    const float* x   = (const float*)d_in[0];
    const int*   ei  = (const int*)d_in[1];
    const float* W1  = (const float*)d_in[2];
    const float* b1  = (const float*)d_in[3];
    const float* Wmu = (const float*)d_in[4];
    const float* bmu = (const float*)d_in[5];
    const float* Wls = (const float*)d_in[6];
    const float* bls = (const float*)d_in[7];
    float* out = (float*)d_out;

    k_count<<<(E_EDGES / 2 + 255) / 256, 256>>>(ei);
    k_scanfuse<<<SCAN_B, 256>>>(x);
    k_fill<<<(E_EDGES + 255) / 256, 256>>>(ei);
    k_fused1<<<(N_NODES + 3) / 4, dim3(96, 4)>>>(W1, b1);
    k_aggh_csr<<<(N_NODES + 3) / 4, dim3(HID, 4)>>>();
    k_out<<<(N_NODES + ONPB - 1) / ONPB, dim3(12, 8)>>>(Wmu, bmu, Wls, bls, out);
}